// round 7
// baseline (speedup 1.0000x reference)
#include <cuda_runtime.h>
#include <math.h>
#include <stdint.h>

#define Bq   8
#define Tq   500
#define Uq   120
#define UP1  121
#define Vq   128
#define Hq   320
#define G4   1280
#define DIN  80
#define VM1  127

#define NCH  10
#define TCH  50
#define DTq  121

// ---------------- static device scratch ----------------
__device__ float g_xp0[Bq * Tq * G4];
__device__ float g_h0 [Bq * Tq * Hq];
__device__ float g_xp1[Bq * Tq * G4];
__device__ float g_h1 [Bq * Tq * Hq];
__device__ float g_enc[Bq * Tq * Vq];
__device__ float g_xpd[Bq * UP1 * G4];
__device__ float g_hd [Bq * UP1 * Hq];
__device__ float g_dec[Bq * UP1 * Vq];
__device__ float g_lb [Bq * Tq * UP1];
__device__ float g_ly [Bq * Tq * Uq];
__device__ float g_nll[Bq];
__device__ float g_alpha[Bq * 128];
// LSTM chunk state: [instance][b][Hq]
__device__ float g_stC0[Bq * Hq];
__device__ float g_stH0[Bq * Hq];
__device__ float g_stC1[Bq * Hq];
__device__ float g_stH1[Bq * Hq];
__device__ float g_stCd[Bq * Hq];
__device__ float g_stHd[Bq * Hq];

__device__ __forceinline__ float sig_f(float x)
{
    return __fdividef(1.f, 1.f + __expf(-x));
}
__device__ __forceinline__ float tanh_f(float x)
{
    float e = __expf(2.f * fabsf(x));
    float r = 1.f - __fdividef(2.f, e + 1.f);
    return copysignf(r, x);
}

// ---------------- tiled GEMM: C[M,N] = A[M,K] @ B[N,K]^T + b1 + b2 -----------------------
// Optional (t0,tlen,Ttot) row mapping: logical row m -> global row b*Ttot + t0 + (m%tlen),
// b = m/tlen. Used to run the GEMM over one t-chunk of the [B,T,*] tensors.
#define GBM 128
#define GBN 64
#define GBK 16

__global__ void __launch_bounds__(256) gemm_nt(const float* __restrict__ A,
                                               const float* __restrict__ Bm,
                                               const float* __restrict__ b1,
                                               const float* __restrict__ b2,
                                               float* __restrict__ C,
                                               int M, int N, int K,
                                               int t0, int tlen, int Ttot)
{
    __shared__ float As[GBK][GBM + 4];
    __shared__ float Bs[GBK][GBN + 4];
    int tid = threadIdx.x;
    int bm = blockIdx.y * GBM;
    int bn = blockIdx.x * GBN;
    int tx = tid & 15, ty = tid >> 4;

    float acc[8][4];
#pragma unroll
    for (int i = 0; i < 8; i++)
#pragma unroll
        for (int j = 0; j < 4; j++) acc[i][j] = 0.f;

    for (int k0 = 0; k0 < K; k0 += GBK) {
#pragma unroll
        for (int l = 0; l < 8; l++) {
            int idx = l * 256 + tid;
            int am = idx >> 4, ak = idx & 15;
            int m = bm + am;
            float v = 0.f;
            if (m < M && k0 + ak < K) {
                size_t grow = (tlen > 0)
                    ? (size_t)(m / tlen) * Ttot + t0 + (m % tlen)
                    : (size_t)m;
                v = A[grow * K + k0 + ak];
            }
            As[ak][am] = v;
        }
#pragma unroll
        for (int l = 0; l < 4; l++) {
            int idx = l * 256 + tid;
            int bnn = idx >> 4, bk = idx & 15;
            float v = 0.f;
            if (bn + bnn < N && k0 + bk < K) v = Bm[(size_t)(bn + bnn) * K + k0 + bk];
            Bs[bk][bnn] = v;
        }
        __syncthreads();
#pragma unroll
        for (int k = 0; k < GBK; k++) {
            float4 a0 = *(const float4*)&As[k][ty * 8];
            float4 a1 = *(const float4*)&As[k][ty * 8 + 4];
            float4 bv = *(const float4*)&Bs[k][tx * 4];
            float af[8] = {a0.x, a0.y, a0.z, a0.w, a1.x, a1.y, a1.z, a1.w};
            float bf[4] = {bv.x, bv.y, bv.z, bv.w};
#pragma unroll
            for (int i = 0; i < 8; i++)
#pragma unroll
                for (int j = 0; j < 4; j++) acc[i][j] += af[i] * bf[j];
        }
        __syncthreads();
    }

    int n0 = bn + tx * 4;
    float bias[4];
#pragma unroll
    for (int j = 0; j < 4; j++)
        bias[j] = (b1 ? b1[n0 + j] : 0.f) + (b2 ? b2[n0 + j] : 0.f);

#pragma unroll
    for (int i = 0; i < 8; i++) {
        int m = bm + ty * 8 + i;
        if (m >= M) continue;
        size_t grow = (tlen > 0)
            ? (size_t)(m / tlen) * Ttot + t0 + (m % tlen)
            : (size_t)m;
        float4 r;
        r.x = acc[i][0] + bias[0];
        r.y = acc[i][1] + bias[1];
        r.z = acc[i][2] + bias[2];
        r.w = acc[i][3] + bias[3];
        *(float4*)&C[grow * N + n0] = r;
    }
}

// ---------------- LSTM: 8-CTA cluster/batch, chunked with gmem-carried state -------------
__global__ void __cluster_dims__(8, 1, 1) __launch_bounds__(320, 1)
lstm_kernel(const float* __restrict__ Whh, const float* __restrict__ xproj,
            float* __restrict__ hout, int Ttot, int t0, int Tc,
            float* __restrict__ stC, float* __restrict__ stH, int init)
{
    __shared__ __align__(16) float hbuf[2][Hq];          // buffer stride 1280 B
    __shared__ __align__(8) unsigned long long mbars[2];

    unsigned rank;
    asm("mov.u32 %0, %%cluster_ctarank;" : "=r"(rank));
    int batch = blockIdx.x >> 3;

    int tid = threadIdx.x;
    int s   = tid & 7;            // K-slice
    int rg  = tid >> 3;           // local unit 0..39
    int unit = (int)rank * 40 + rg;

    // register-resident weights: 4 gates x 40 K = 160 floats as 80 u64 (K-paired)
    unsigned long long w[4][20];
#pragma unroll
    for (int r = 0; r < 4; r++) {
        const ulonglong2* p = reinterpret_cast<const ulonglong2*>(
            Whh + (size_t)(r * Hq + unit) * Hq + s * 40);
#pragma unroll
        for (int i = 0; i < 10; i++) {
            ulonglong2 u = p[i];
            w[r][2 * i] = u.x; w[r][2 * i + 1] = u.y;
        }
    }

    hbuf[0][tid] = init ? 0.f : stH[batch * Hq + tid];
    float c = init ? 0.f : stC[batch * Hq + unit];

    unsigned mb_local = (unsigned)__cvta_generic_to_shared(&mbars[0]);
    if (tid == 0) {
        asm volatile("mbarrier.init.shared.b64 [%0], 1;" :: "r"(mb_local) : "memory");
        asm volatile("mbarrier.init.shared.b64 [%0], 1;" :: "r"(mb_local + 8) : "memory");
    }

    const float* xpb = xproj + ((size_t)batch * Ttot) * G4 + unit;
    float xg0 = 0.f, xg1 = 0.f, xg2 = 0.f, xg3 = 0.f;
    if (s == 0) {
        const float* xq = xpb + (size_t)t0 * G4;
        xg0 = __ldg(xq);
        xg1 = __ldg(xq + Hq);
        xg2 = __ldg(xq + 2 * Hq);
        xg3 = __ldg(xq + 3 * Hq);
    }

    unsigned h_local = (unsigned)__cvta_generic_to_shared(&hbuf[0][unit]);

    __syncthreads();
    asm volatile("barrier.cluster.arrive.aligned;" ::: "memory");
    asm volatile("barrier.cluster.wait.aligned;" ::: "memory");

    unsigned ph0 = 0, ph1 = 0;
    float h = 0.f;

    for (int k = 0; k < Tc; k++) {
        int t = t0 + k;
        int cur = k & 1, nxt = cur ^ 1;
        int not_last = (k + 1 < Tc);

        if (not_last && tid == 0)
            asm volatile("mbarrier.arrive.expect_tx.shared.b64 _, [%0], 1280;"
                         :: "r"(mb_local + (unsigned)nxt * 8) : "memory");

        const ulonglong2* h2 =
            reinterpret_cast<const ulonglong2*>(&hbuf[cur][s * 40]);
        unsigned long long a0 = 0ULL, a1 = 0ULL, a2 = 0ULL, a3 = 0ULL;
#pragma unroll
        for (int i = 0; i < 10; i++) {
            ulonglong2 hv = h2[i];
            asm("fma.rn.f32x2 %0, %1, %2, %0;" : "+l"(a0) : "l"(w[0][2*i]),   "l"(hv.x));
            asm("fma.rn.f32x2 %0, %1, %2, %0;" : "+l"(a1) : "l"(w[1][2*i]),   "l"(hv.x));
            asm("fma.rn.f32x2 %0, %1, %2, %0;" : "+l"(a2) : "l"(w[2][2*i]),   "l"(hv.x));
            asm("fma.rn.f32x2 %0, %1, %2, %0;" : "+l"(a3) : "l"(w[3][2*i]),   "l"(hv.x));
            asm("fma.rn.f32x2 %0, %1, %2, %0;" : "+l"(a0) : "l"(w[0][2*i+1]), "l"(hv.y));
            asm("fma.rn.f32x2 %0, %1, %2, %0;" : "+l"(a1) : "l"(w[1][2*i+1]), "l"(hv.y));
            asm("fma.rn.f32x2 %0, %1, %2, %0;" : "+l"(a2) : "l"(w[2][2*i+1]), "l"(hv.y));
            asm("fma.rn.f32x2 %0, %1, %2, %0;" : "+l"(a3) : "l"(w[3][2*i+1]), "l"(hv.y));
        }
        float g0, g1, g2, g3;
        {
            unsigned lo, hi;
            asm("mov.b64 {%0,%1}, %2;" : "=r"(lo), "=r"(hi) : "l"(a0));
            g0 = __uint_as_float(lo) + __uint_as_float(hi);
            asm("mov.b64 {%0,%1}, %2;" : "=r"(lo), "=r"(hi) : "l"(a1));
            g1 = __uint_as_float(lo) + __uint_as_float(hi);
            asm("mov.b64 {%0,%1}, %2;" : "=r"(lo), "=r"(hi) : "l"(a2));
            g2 = __uint_as_float(lo) + __uint_as_float(hi);
            asm("mov.b64 {%0,%1}, %2;" : "=r"(lo), "=r"(hi) : "l"(a3));
            g3 = __uint_as_float(lo) + __uint_as_float(hi);
        }
        if (s == 0) { g0 += xg0; g1 += xg1; g2 += xg2; g3 += xg3; }

        if (s == 0 && not_last) {
            const float* xq = xpb + (size_t)(t + 1) * G4;
            xg0 = __ldg(xq);
            xg1 = __ldg(xq + Hq);
            xg2 = __ldg(xq + 2 * Hq);
            xg3 = __ldg(xq + 3 * Hq);
        }

#pragma unroll
        for (int d = 1; d < 8; d <<= 1) {
            g0 += __shfl_xor_sync(0xffffffffu, g0, d);
            g1 += __shfl_xor_sync(0xffffffffu, g1, d);
            g2 += __shfl_xor_sync(0xffffffffu, g2, d);
            g3 += __shfl_xor_sync(0xffffffffu, g3, d);
        }

        float i_ = sig_f(g0);
        float f_ = sig_f(g1);
        float gg = tanh_f(g2);
        float o_ = sig_f(g3);
        c = f_ * c + i_ * gg;
        h = o_ * tanh_f(c);

        if (s == 0) {
            hout[((size_t)batch * Ttot + t) * Hq + unit] = h;
            if (not_last) {
                unsigned hbits = __float_as_uint(h);
                unsigned doff = (unsigned)nxt * (Hq * 4);
                unsigned moff = (unsigned)nxt * 8;
#pragma unroll
                for (int r = 0; r < 8; r++) {
                    unsigned rh, rm;
                    asm("mapa.shared::cluster.u32 %0, %1, %2;"
                        : "=r"(rh) : "r"(h_local), "r"(r));
                    asm("mapa.shared::cluster.u32 %0, %1, %2;"
                        : "=r"(rm) : "r"(mb_local), "r"(r));
                    asm volatile(
                        "st.async.shared::cluster.mbarrier::complete_tx::bytes.b32 "
                        "[%0], %1, [%2];"
                        :: "r"(rh + doff), "r"(hbits), "r"(rm + moff) : "memory");
                }
            }
        }

        if (not_last) {
            unsigned par = nxt ? ph1 : ph0;
            unsigned mb  = mb_local + (unsigned)nxt * 8;
            asm volatile(
                "{\n\t.reg .pred P;\n\t"
                "WL_%=:\n\t"
                "mbarrier.try_wait.parity.acquire.cta.shared::cta.b64 P, [%0], %1, 0x989680;\n\t"
                "@!P bra WL_%=;\n\t}"
                :: "r"(mb), "r"(par) : "memory");
            if (nxt) ph1 ^= 1; else ph0 ^= 1;
        }
    }

    // persist state for next chunk
    if (s == 0) {
        stH[batch * Hq + unit] = h;
        stC[batch * Hq + unit] = c;
    }
}

// ---------------- decoder xproj via embedding gather (one-hot rows) ----------------
__global__ void __launch_bounds__(256) xpd_kernel(const int* __restrict__ ys,
                                                  const float* __restrict__ Wih,
                                                  const float* __restrict__ bih,
                                                  const float* __restrict__ bhh)
{
    int b = blockIdx.x / UP1, u = blockIdx.x % UP1;
    int id = (u == 0) ? 0 : ys[b * Uq + u - 1];
    float* dst = g_xpd + ((size_t)b * UP1 + u) * G4;
    for (int g = threadIdx.x; g < G4; g += 256) {
        float v = bih[g] + bhh[g];
        if (id > 0) v += Wih[(size_t)g * VM1 + (id - 1)];
        dst[g] = v;
    }
}

// ---------------- joint + log-softmax -> lb (blank) and ly (label), per t-chunk ----------
__global__ void __launch_bounds__(128) joint_kernel(const int* __restrict__ ys, int t0)
{
    int b = blockIdx.y;
    int t = t0 + blockIdx.x * 4 + (threadIdx.x >> 5);
    if (t >= t0 + TCH || t >= Tq) return;
    int lane = threadIdx.x & 31;

    const float* e = g_enc + ((size_t)b * Tq + t) * Vq;
    float e0 = e[lane], e1 = e[32 + lane], e2 = e[64 + lane], e3 = e[96 + lane];
    float* lbp = g_lb + ((size_t)b * Tq + t) * UP1;
    float* lyp = g_ly + ((size_t)b * Tq + t) * Uq;

    for (int u = 0; u < UP1; u++) {
        const float* d = g_dec + ((size_t)b * UP1 + u) * Vq;
        float j0 = e0 + d[lane];
        float j1 = e1 + d[32 + lane];
        float j2 = e2 + d[64 + lane];
        float j3 = e3 + d[96 + lane];

        float m = fmaxf(fmaxf(j0, j1), fmaxf(j2, j3));
#pragma unroll
        for (int dlt = 16; dlt > 0; dlt >>= 1)
            m = fmaxf(m, __shfl_xor_sync(0xffffffffu, m, dlt));
        float sm = __expf(j0 - m) + __expf(j1 - m) + __expf(j2 - m) + __expf(j3 - m);
#pragma unroll
        for (int dlt = 16; dlt > 0; dlt >>= 1)
            sm += __shfl_xor_sync(0xffffffffu, sm, dlt);
        float logZ = m + __logf(sm);

        if (lane == 0) lbp[u] = j0 - logZ;
        if (u < Uq) {
            int lbl = ys[b * Uq + u];
            int k = lbl >> 5, src = lbl & 31;
            float jv = (k == 0) ? j0 : (k == 1) ? j1 : (k == 2) ? j2 : j3;
            jv = __shfl_sync(0xffffffffu, jv, src);
            if (lane == 0) lyp[u] = jv - logZ;
        }
    }
}

// ---------------- RNN-T alpha recursion, chunked over t with gmem state ------------------
__device__ __forceinline__ float lsef(float a, float b)
{
    float mx = fmaxf(a, b), mn = fminf(a, b);
    return mx + __logf(1.f + __expf(mn - mx));
}

__global__ void __launch_bounds__(32) alpha_kernel(const int* __restrict__ xlen,
                                                   const int* __restrict__ ylen,
                                                   int t0, int tlen)
{
    const float BIG = -1e30f;
    int b = blockIdx.x;
    int lane = threadIdx.x;
    int tl = xlen[b], ul = ylen[b];
    if (t0 >= tl) return;
    const float* lbB = g_lb + (size_t)b * Tq * UP1;
    const float* lyB = g_ly + (size_t)b * Tq * Uq;
    int idx0 = lane * 4;

    float a[4];
    int tstart;
    if (t0 == 0) {
        float e[4];
#pragma unroll
        for (int j = 0; j < 4; j++) {
            int idx = idx0 + j;
            e[j] = (idx >= 1 && idx <= Uq) ? __ldg(&lyB[idx - 1]) : 0.f;
        }
        float s[4];
        s[0] = e[0]; s[1] = s[0] + e[1]; s[2] = s[1] + e[2]; s[3] = s[2] + e[3];
        float v = s[3];
#pragma unroll
        for (int d = 1; d < 32; d <<= 1) {
            float t2 = __shfl_up_sync(0xffffffffu, v, d);
            if (lane >= d) v += t2;
        }
        float base = v - s[3];
#pragma unroll
        for (int j = 0; j < 4; j++) a[j] = base + s[j];
        tstart = 1;
    } else {
#pragma unroll
        for (int j = 0; j < 4; j++) a[j] = g_alpha[b * 128 + idx0 + j];
        tstart = t0;
    }

    int tend = (t0 + tlen < tl) ? (t0 + tlen) : tl;
    for (int t = tstart; t < tend; t++) {
        const float* lyr = lyB + (size_t)t * Uq;
        const float* lbr = lbB + (size_t)(t - 1) * UP1;
        float e[4], lbv[4];
#pragma unroll
        for (int j = 0; j < 4; j++) {
            int idx = idx0 + j;
            e[j]   = (idx >= 1 && idx <= Uq) ? __ldg(&lyr[idx - 1]) : 0.f;
            lbv[j] = (idx < UP1) ? __ldg(&lbr[idx]) : 0.f;
        }
        float s[4];
        s[0] = e[0]; s[1] = s[0] + e[1]; s[2] = s[1] + e[2]; s[3] = s[2] + e[3];
        float v = s[3];
#pragma unroll
        for (int d = 1; d < 32; d <<= 1) {
            float t2 = __shfl_up_sync(0xffffffffu, v, d);
            if (lane >= d) v += t2;
        }
        float base = v - s[3];
        float cj[4];
#pragma unroll
        for (int j = 0; j < 4; j++) cj[j] = base + s[j];

        float x[4], m[4];
#pragma unroll
        for (int j = 0; j < 4; j++) {
            int idx = idx0 + j;
            x[j] = (idx < UP1) ? (a[j] + lbv[j] - cj[j]) : BIG;
        }
        m[0] = x[0];
        m[1] = lsef(m[0], x[1]);
        m[2] = lsef(m[1], x[2]);
        m[3] = lsef(m[2], x[3]);
        float z = m[3];
#pragma unroll
        for (int d = 1; d < 32; d <<= 1) {
            float t2 = __shfl_up_sync(0xffffffffu, z, d);
            if (lane >= d) z = lsef(z, t2);
        }
        float excl = __shfl_up_sync(0xffffffffu, z, 1);
        if (lane == 0) excl = BIG;
#pragma unroll
        for (int j = 0; j < 4; j++) a[j] = cj[j] + lsef(excl, m[j]);
    }

#pragma unroll
    for (int j = 0; j < 4; j++) g_alpha[b * 128 + idx0 + j] = a[j];

    if (tl <= t0 + tlen) {
        float sel = a[ul & 3];
        float aul = __shfl_sync(0xffffffffu, sel, ul >> 2);
        if (lane == 0)
            g_nll[b] = -(aul + __ldg(&lbB[(size_t)(tl - 1) * UP1 + ul]));
    }
}

__global__ void mean_kernel(float* __restrict__ out)
{
    float s = 0.f;
    for (int b = 0; b < Bq; b++) s += g_nll[b];
    out[0] = s / (float)Bq;
}

// ---------------- launch: chunked 3-stream pipeline ----------------
extern "C" void kernel_launch(void* const* d_in, const int* in_sizes, int n_in,
                              void* d_out, int out_size)
{
    const float* xs    = (const float*)d_in[0];
    const int*   ys    = (const int*)  d_in[1];
    const int*   xlen  = (const int*)  d_in[2];
    const int*   ylen  = (const int*)  d_in[3];
    const float* eWih0 = (const float*)d_in[4];
    const float* eWhh0 = (const float*)d_in[5];
    const float* ebih0 = (const float*)d_in[6];
    const float* ebhh0 = (const float*)d_in[7];
    const float* eWih1 = (const float*)d_in[8];
    const float* eWhh1 = (const float*)d_in[9];
    const float* ebih1 = (const float*)d_in[10];
    const float* ebhh1 = (const float*)d_in[11];
    const float* eWo   = (const float*)d_in[12];
    const float* ebo   = (const float*)d_in[13];
    /* d_in[14] = embed (one-hot; folded into xpd gather) */
    const float* dWih  = (const float*)d_in[15];
    const float* dWhh  = (const float*)d_in[16];
    const float* dbih  = (const float*)d_in[17];
    const float* dbhh  = (const float*)d_in[18];
    const float* dWo   = (const float*)d_in[19];
    const float* dbo   = (const float*)d_in[20];
    float* out = (float*)d_out;

    float *xp0, *h0, *xp1, *h1, *enc, *xpd, *hd, *dec;
    float *sC0, *sH0, *sC1, *sH1, *sCd, *sHd;
    cudaGetSymbolAddress((void**)&xp0, g_xp0);
    cudaGetSymbolAddress((void**)&h0,  g_h0);
    cudaGetSymbolAddress((void**)&xp1, g_xp1);
    cudaGetSymbolAddress((void**)&h1,  g_h1);
    cudaGetSymbolAddress((void**)&enc, g_enc);
    cudaGetSymbolAddress((void**)&xpd, g_xpd);
    cudaGetSymbolAddress((void**)&hd,  g_hd);
    cudaGetSymbolAddress((void**)&dec, g_dec);
    cudaGetSymbolAddress((void**)&sC0, g_stC0);
    cudaGetSymbolAddress((void**)&sH0, g_stH0);
    cudaGetSymbolAddress((void**)&sC1, g_stC1);
    cudaGetSymbolAddress((void**)&sH1, g_stH1);
    cudaGetSymbolAddress((void**)&sCd, g_stCd);
    cudaGetSymbolAddress((void**)&sHd, g_stHd);

    // one-time stream/event creation (first call is the uncaptured correctness run)
    static cudaStream_t s1 = nullptr, s2 = nullptr;
    static cudaEvent_t Efork, E0[NCH], E1[NCH], E2;
    static int inited = 0;
    if (!inited) {
        cudaStreamCreateWithFlags(&s1, cudaStreamNonBlocking);
        cudaStreamCreateWithFlags(&s2, cudaStreamNonBlocking);
        cudaEventCreateWithFlags(&Efork, cudaEventDisableTiming);
        cudaEventCreateWithFlags(&E2, cudaEventDisableTiming);
        for (int c = 0; c < NCH; c++) {
            cudaEventCreateWithFlags(&E0[c], cudaEventDisableTiming);
            cudaEventCreateWithFlags(&E1[c], cudaEventDisableTiming);
        }
        inited = 1;
    }

    const int MT = Bq * Tq;       // 4000
    const int MU = Bq * UP1;      // 968
    const int MC = Bq * TCH;      // 400 rows per chunk

    cudaStream_t s0 = 0;

    // fork point
    cudaEventRecord(Efork, s0);
    cudaStreamWaitEvent(s1, Efork, 0);
    cudaStreamWaitEvent(s2, Efork, 0);

    // S0 head: full xp0 GEMM (feeds all enc0 chunks)
    gemm_nt<<<dim3(G4 / GBN, (MT + GBM - 1) / GBM), 256, 0, s0>>>(
        xs, eWih0, ebih0, ebhh0, xp0, MT, G4, DIN, 0, 0, 0);

    // S2 head: decoder branch (concurrent with enc0 chunk 0; 64+64 CTAs <= 152 SMs)
    xpd_kernel<<<Bq * UP1, 256, 0, s2>>>(ys, dWih, dbih, dbhh);
    lstm_kernel<<<64, 320, 0, s2>>>(dWhh, xpd, hd, DTq, 0, DTq, sCd, sHd, 1);
    gemm_nt<<<dim3(Vq / GBN, (MU + GBM - 1) / GBM), 256, 0, s2>>>(
        hd, dWo, dbo, nullptr, dec, MU, Vq, Hq, 0, 0, 0);

    for (int c = 0; c < NCH; c++) {
        int t0 = c * TCH;

        // S0: enc0 chunk
        lstm_kernel<<<64, 320, 0, s0>>>(eWhh0, xp0, h0, Tq, t0, TCH, sC0, sH0, c == 0);
        cudaEventRecord(E0[c], s0);

        // S1: xp1(chunk) -> enc1 chunk -> enc proj(chunk)
        cudaStreamWaitEvent(s1, E0[c], 0);
        gemm_nt<<<dim3(G4 / GBN, (MC + GBM - 1) / GBM), 256, 0, s1>>>(
            h0, eWih1, ebih1, ebhh1, xp1, MC, G4, Hq, t0, TCH, Tq);
        lstm_kernel<<<64, 320, 0, s1>>>(eWhh1, xp1, h1, Tq, t0, TCH, sC1, sH1, c == 0);
        gemm_nt<<<dim3(Vq / GBN, (MC + GBM - 1) / GBM), 256, 0, s1>>>(
            h1, eWo, ebo, nullptr, enc, MC, Vq, Hq, t0, TCH, Tq);
        cudaEventRecord(E1[c], s1);

        // S2: joint(chunk) -> alpha(chunk)
        cudaStreamWaitEvent(s2, E1[c], 0);
        joint_kernel<<<dim3((TCH + 3) / 4, Bq), 128, 0, s2>>>(ys, t0);
        alpha_kernel<<<Bq, 32, 0, s2>>>(xlen, ylen, t0, TCH);
    }

    // join and finish
    cudaEventRecord(E2, s2);
    cudaStreamWaitEvent(s0, E2, 0);
    mean_kernel<<<1, 1, 0, s0>>>(out);
}

// round 8
// speedup vs baseline: 1.2972x; 1.2972x over previous
#include <cuda_runtime.h>
#include <math.h>
#include <stdint.h>

#define Bq   8
#define Tq   500
#define Uq   120
#define UP1  121
#define Vq   128
#define Hq   320
#define G4   1280
#define DIN  80
#define VM1  127
#define DTq  121

// ---------------- static device scratch ----------------
__device__ float g_xp0[Bq * Tq * G4];
__device__ float g_h0 [Bq * Tq * Hq];
__device__ float g_xp1[Bq * Tq * G4];
__device__ float g_h1 [Bq * Tq * Hq];
__device__ float g_enc[Bq * Tq * Vq];
__device__ float g_xpd[Bq * UP1 * G4];
__device__ float g_hd [Bq * UP1 * Hq];
__device__ float g_dec[Bq * UP1 * Vq];
__device__ float g_lb [Bq * Tq * UP1];
__device__ float g_ly [Bq * Tq * Uq];
__device__ float g_nll[Bq];

__device__ __forceinline__ float sig_f(float x)
{
    return __fdividef(1.f, 1.f + __expf(-x));
}
__device__ __forceinline__ float tanh_f(float x)
{
    float e = __expf(2.f * fabsf(x));
    float r = 1.f - __fdividef(2.f, e + 1.f);
    return copysignf(r, x);
}

// ---------------- tiled GEMM: C[M,N] = A[M,K] @ B[N,K]^T + b1 + b2 ----------------
#define GBM 128
#define GBN 64
#define GBK 16

__global__ void __launch_bounds__(256) gemm_nt(const float* __restrict__ A,
                                               const float* __restrict__ Bm,
                                               const float* __restrict__ b1,
                                               const float* __restrict__ b2,
                                               float* __restrict__ C,
                                               int M, int N, int K)
{
    __shared__ float As[GBK][GBM + 4];
    __shared__ float Bs[GBK][GBN + 4];
    int tid = threadIdx.x;
    int bm = blockIdx.y * GBM;
    int bn = blockIdx.x * GBN;
    int tx = tid & 15, ty = tid >> 4;

    float acc[8][4];
#pragma unroll
    for (int i = 0; i < 8; i++)
#pragma unroll
        for (int j = 0; j < 4; j++) acc[i][j] = 0.f;

    for (int k0 = 0; k0 < K; k0 += GBK) {
#pragma unroll
        for (int l = 0; l < 8; l++) {
            int idx = l * 256 + tid;
            int am = idx >> 4, ak = idx & 15;
            float v = 0.f;
            if (bm + am < M && k0 + ak < K) v = A[(size_t)(bm + am) * K + k0 + ak];
            As[ak][am] = v;
        }
#pragma unroll
        for (int l = 0; l < 4; l++) {
            int idx = l * 256 + tid;
            int bnn = idx >> 4, bk = idx & 15;
            float v = 0.f;
            if (bn + bnn < N && k0 + bk < K) v = Bm[(size_t)(bn + bnn) * K + k0 + bk];
            Bs[bk][bnn] = v;
        }
        __syncthreads();
#pragma unroll
        for (int k = 0; k < GBK; k++) {
            float4 a0 = *(const float4*)&As[k][ty * 8];
            float4 a1 = *(const float4*)&As[k][ty * 8 + 4];
            float4 bv = *(const float4*)&Bs[k][tx * 4];
            float af[8] = {a0.x, a0.y, a0.z, a0.w, a1.x, a1.y, a1.z, a1.w};
            float bf[4] = {bv.x, bv.y, bv.z, bv.w};
#pragma unroll
            for (int i = 0; i < 8; i++)
#pragma unroll
                for (int j = 0; j < 4; j++) acc[i][j] += af[i] * bf[j];
        }
        __syncthreads();
    }

    int n0 = bn + tx * 4;
    float bias[4];
#pragma unroll
    for (int j = 0; j < 4; j++)
        bias[j] = (b1 ? b1[n0 + j] : 0.f) + (b2 ? b2[n0 + j] : 0.f);

#pragma unroll
    for (int i = 0; i < 8; i++) {
        int m = bm + ty * 8 + i;
        if (m >= M) continue;
        float4 r;
        r.x = acc[i][0] + bias[0];
        r.y = acc[i][1] + bias[1];
        r.z = acc[i][2] + bias[2];
        r.w = acc[i][3] + bias[3];
        *(float4*)&C[(size_t)m * N + n0] = r;
    }
}

// ---------------- LSTM: 16-CTA cluster per batch ----------------------------------------
// 20 units/CTA. thread = (s = tid&15: K-slice of 20, rg = tid>>4: unit). 80 weight floats
// per thread -> guaranteed register residency (~120 regs << 204 cap). 4-step shfl
// butterfly combines the 16 K-slices; every lane then holds the gates -> redundant
// activations and c. Broadcast: thread (s,rg) st.asyncs unit rg's h to CTA s.
__global__ void __launch_bounds__(320, 1)
lstm16_kernel(const float* __restrict__ Whh, const float* __restrict__ xproj,
              float* __restrict__ hout, int T)
{
    __shared__ __align__(16) float hbuf[2][Hq];          // buffer stride 1280 B
    __shared__ __align__(8) unsigned long long mbars[2];

    unsigned rank;
    asm("mov.u32 %0, %%cluster_ctarank;" : "=r"(rank));
    int batch = blockIdx.x >> 4;

    int tid = threadIdx.x;
    int s   = tid & 15;           // K-slice (20 wide)
    int rg  = tid >> 4;           // local unit 0..19
    int unit = (int)rank * 20 + rg;

    // register-resident weights: 4 gates x 20 K = 80 floats as 40 u64
    unsigned long long w[4][10];
#pragma unroll
    for (int r = 0; r < 4; r++) {
        const ulonglong2* p = reinterpret_cast<const ulonglong2*>(
            Whh + (size_t)(r * Hq + unit) * Hq + s * 20);
#pragma unroll
        for (int i = 0; i < 5; i++) {
            ulonglong2 u = p[i];
            w[r][2 * i] = u.x; w[r][2 * i + 1] = u.y;
        }
    }

    hbuf[0][tid] = 0.f;
    float c = 0.f;

    unsigned mb_local = (unsigned)__cvta_generic_to_shared(&mbars[0]);
    if (tid == 0) {
        asm volatile("mbarrier.init.shared.b64 [%0], 1;" :: "r"(mb_local) : "memory");
        asm volatile("mbarrier.init.shared.b64 [%0], 1;" :: "r"(mb_local + 8) : "memory");
    }

    const float* xpb = xproj + ((size_t)batch * T) * G4 + unit;
    float xg0 = 0.f, xg1 = 0.f, xg2 = 0.f, xg3 = 0.f;
    if (s == 0) {
        xg0 = __ldg(xpb);
        xg1 = __ldg(xpb + Hq);
        xg2 = __ldg(xpb + 2 * Hq);
        xg3 = __ldg(xpb + 3 * Hq);
    }

    // per-thread fixed destination: CTA 's', slot = my unit
    unsigned h_local = (unsigned)__cvta_generic_to_shared(&hbuf[0][unit]);
    unsigned rh, rm;
    asm("mapa.shared::cluster.u32 %0, %1, %2;" : "=r"(rh) : "r"(h_local), "r"(s));
    asm("mapa.shared::cluster.u32 %0, %1, %2;" : "=r"(rm) : "r"(mb_local), "r"(s));

    __syncthreads();
    asm volatile("barrier.cluster.arrive.aligned;" ::: "memory");
    asm volatile("barrier.cluster.wait.aligned;" ::: "memory");

    unsigned ph0 = 0, ph1 = 0;

    for (int t = 0; t < T; t++) {
        int cur = t & 1, nxt = cur ^ 1;
        int not_last = (t + 1 < T);

        if (not_last && tid == 0)
            asm volatile("mbarrier.arrive.expect_tx.shared.b64 _, [%0], 1280;"
                         :: "r"(mb_local + (unsigned)nxt * 8) : "memory");

        // matvec: 4 gate rows x 20 K, f32x2 packed
        const ulonglong2* h2 =
            reinterpret_cast<const ulonglong2*>(&hbuf[cur][s * 20]);
        unsigned long long a0 = 0ULL, a1 = 0ULL, a2 = 0ULL, a3 = 0ULL;
#pragma unroll
        for (int i = 0; i < 5; i++) {
            ulonglong2 hv = h2[i];
            asm("fma.rn.f32x2 %0, %1, %2, %0;" : "+l"(a0) : "l"(w[0][2*i]),   "l"(hv.x));
            asm("fma.rn.f32x2 %0, %1, %2, %0;" : "+l"(a1) : "l"(w[1][2*i]),   "l"(hv.x));
            asm("fma.rn.f32x2 %0, %1, %2, %0;" : "+l"(a2) : "l"(w[2][2*i]),   "l"(hv.x));
            asm("fma.rn.f32x2 %0, %1, %2, %0;" : "+l"(a3) : "l"(w[3][2*i]),   "l"(hv.x));
            asm("fma.rn.f32x2 %0, %1, %2, %0;" : "+l"(a0) : "l"(w[0][2*i+1]), "l"(hv.y));
            asm("fma.rn.f32x2 %0, %1, %2, %0;" : "+l"(a1) : "l"(w[1][2*i+1]), "l"(hv.y));
            asm("fma.rn.f32x2 %0, %1, %2, %0;" : "+l"(a2) : "l"(w[2][2*i+1]), "l"(hv.y));
            asm("fma.rn.f32x2 %0, %1, %2, %0;" : "+l"(a3) : "l"(w[3][2*i+1]), "l"(hv.y));
        }
        float g0, g1, g2, g3;
        {
            unsigned lo, hi;
            asm("mov.b64 {%0,%1}, %2;" : "=r"(lo), "=r"(hi) : "l"(a0));
            g0 = __uint_as_float(lo) + __uint_as_float(hi);
            asm("mov.b64 {%0,%1}, %2;" : "=r"(lo), "=r"(hi) : "l"(a1));
            g1 = __uint_as_float(lo) + __uint_as_float(hi);
            asm("mov.b64 {%0,%1}, %2;" : "=r"(lo), "=r"(hi) : "l"(a2));
            g2 = __uint_as_float(lo) + __uint_as_float(hi);
            asm("mov.b64 {%0,%1}, %2;" : "=r"(lo), "=r"(hi) : "l"(a3));
            g3 = __uint_as_float(lo) + __uint_as_float(hi);
        }
        if (s == 0) { g0 += xg0; g1 += xg1; g2 += xg2; g3 += xg3; }

        // prefetch next-step xproj
        if (s == 0 && not_last) {
            const float* xq = xpb + (size_t)(t + 1) * G4;
            xg0 = __ldg(xq);
            xg1 = __ldg(xq + Hq);
            xg2 = __ldg(xq + 2 * Hq);
            xg3 = __ldg(xq + 3 * Hq);
        }

        // butterfly over the 16 slice lanes
#pragma unroll
        for (int d = 1; d < 16; d <<= 1) {
            g0 += __shfl_xor_sync(0xffffffffu, g0, d);
            g1 += __shfl_xor_sync(0xffffffffu, g1, d);
            g2 += __shfl_xor_sync(0xffffffffu, g2, d);
            g3 += __shfl_xor_sync(0xffffffffu, g3, d);
        }

        float i_ = sig_f(g0);
        float f_ = sig_f(g1);
        float gg = tanh_f(g2);
        float o_ = sig_f(g3);
        c = f_ * c + i_ * gg;
        float h = o_ * tanh_f(c);

        if (s == 0)
            hout[((size_t)batch * T + t) * Hq + unit] = h;

        if (not_last) {
            // distributed broadcast: this thread delivers unit 'unit' to CTA 's'
            unsigned hbits = __float_as_uint(h);
            asm volatile(
                "st.async.shared::cluster.mbarrier::complete_tx::bytes.b32 "
                "[%0], %1, [%2];"
                :: "r"(rh + (unsigned)nxt * (Hq * 4)), "r"(hbits),
                   "r"(rm + (unsigned)nxt * 8) : "memory");

            unsigned par = nxt ? ph1 : ph0;
            unsigned mb  = mb_local + (unsigned)nxt * 8;
            asm volatile(
                "{\n\t.reg .pred P;\n\t"
                "WL_%=:\n\t"
                "mbarrier.try_wait.parity.acquire.cta.shared::cta.b64 P, [%0], %1, 0x989680;\n\t"
                "@!P bra WL_%=;\n\t}"
                :: "r"(mb), "r"(par) : "memory");
            if (nxt) ph1 ^= 1; else ph0 ^= 1;
        }
    }
}

// ---------------- decoder xproj via embedding gather (one-hot rows) ----------------
__global__ void __launch_bounds__(256) xpd_kernel(const int* __restrict__ ys,
                                                  const float* __restrict__ Wih,
                                                  const float* __restrict__ bih,
                                                  const float* __restrict__ bhh)
{
    int b = blockIdx.x / UP1, u = blockIdx.x % UP1;
    int id = (u == 0) ? 0 : ys[b * Uq + u - 1];
    float* dst = g_xpd + ((size_t)b * UP1 + u) * G4;
    for (int g = threadIdx.x; g < G4; g += 256) {
        float v = bih[g] + bhh[g];
        if (id > 0) v += Wih[(size_t)g * VM1 + (id - 1)];
        dst[g] = v;
    }
}

// ---------------- joint + log-softmax -> lb (blank) and ly (label) only ----------------
__global__ void __launch_bounds__(128) joint_kernel(const int* __restrict__ ys)
{
    int b = blockIdx.y;
    int t = blockIdx.x * 4 + (threadIdx.x >> 5);
    int lane = threadIdx.x & 31;

    const float* e = g_enc + ((size_t)b * Tq + t) * Vq;
    float e0 = e[lane], e1 = e[32 + lane], e2 = e[64 + lane], e3 = e[96 + lane];
    float* lbp = g_lb + ((size_t)b * Tq + t) * UP1;
    float* lyp = g_ly + ((size_t)b * Tq + t) * Uq;

    for (int u = 0; u < UP1; u++) {
        const float* d = g_dec + ((size_t)b * UP1 + u) * Vq;
        float j0 = e0 + d[lane];
        float j1 = e1 + d[32 + lane];
        float j2 = e2 + d[64 + lane];
        float j3 = e3 + d[96 + lane];

        float m = fmaxf(fmaxf(j0, j1), fmaxf(j2, j3));
#pragma unroll
        for (int dlt = 16; dlt > 0; dlt >>= 1)
            m = fmaxf(m, __shfl_xor_sync(0xffffffffu, m, dlt));
        float sm = __expf(j0 - m) + __expf(j1 - m) + __expf(j2 - m) + __expf(j3 - m);
#pragma unroll
        for (int dlt = 16; dlt > 0; dlt >>= 1)
            sm += __shfl_xor_sync(0xffffffffu, sm, dlt);
        float logZ = m + __logf(sm);

        if (lane == 0) lbp[u] = j0 - logZ;
        if (u < Uq) {
            int lbl = ys[b * Uq + u];
            int k = lbl >> 5, src = lbl & 31;
            float jv = (k == 0) ? j0 : (k == 1) ? j1 : (k == 2) ? j2 : j3;
            jv = __shfl_sync(0xffffffffu, jv, src);
            if (lane == 0) lyp[u] = jv - logZ;
        }
    }
}

// ---------------- RNN-T alpha recursion: 1 warp/batch, 4 elems/lane ----------------
__device__ __forceinline__ float lsef(float a, float b)
{
    float mx = fmaxf(a, b), mn = fminf(a, b);
    return mx + __logf(1.f + __expf(mn - mx));
}

__global__ void __launch_bounds__(32) alpha_kernel(const int* __restrict__ xlen,
                                                   const int* __restrict__ ylen)
{
    const float BIG = -1e30f;
    int b = blockIdx.x;
    int lane = threadIdx.x;
    int tl = xlen[b], ul = ylen[b];
    const float* lbB = g_lb + (size_t)b * Tq * UP1;
    const float* lyB = g_ly + (size_t)b * Tq * Uq;
    int idx0 = lane * 4;

    float a[4];
    {   // row 0
        float e[4];
#pragma unroll
        for (int j = 0; j < 4; j++) {
            int idx = idx0 + j;
            e[j] = (idx >= 1 && idx <= Uq) ? __ldg(&lyB[idx - 1]) : 0.f;
        }
        float sc[4];
        sc[0] = e[0]; sc[1] = sc[0] + e[1]; sc[2] = sc[1] + e[2]; sc[3] = sc[2] + e[3];
        float v = sc[3];
#pragma unroll
        for (int d = 1; d < 32; d <<= 1) {
            float t2 = __shfl_up_sync(0xffffffffu, v, d);
            if (lane >= d) v += t2;
        }
        float base = v - sc[3];
#pragma unroll
        for (int j = 0; j < 4; j++) a[j] = base + sc[j];
    }

    float e[4], lbv[4];
    {
        const float* lyr = lyB + (size_t)1 * Uq;
        const float* lbr = lbB;
#pragma unroll
        for (int j = 0; j < 4; j++) {
            int idx = idx0 + j;
            e[j]   = (idx >= 1 && idx <= Uq) ? __ldg(&lyr[idx - 1]) : 0.f;
            lbv[j] = (idx < UP1) ? __ldg(&lbr[idx]) : 0.f;
        }
    }

    for (int t = 1; t < tl; t++) {
        float en[4], lbn[4];
        if (t + 1 < tl) {
            const float* lyr2 = lyB + (size_t)(t + 1) * Uq;
            const float* lbr2 = lbB + (size_t)t * UP1;
#pragma unroll
            for (int j = 0; j < 4; j++) {
                int idx = idx0 + j;
                en[j]  = (idx >= 1 && idx <= Uq) ? __ldg(&lyr2[idx - 1]) : 0.f;
                lbn[j] = (idx < UP1) ? __ldg(&lbr2[idx]) : 0.f;
            }
        }

        float sc[4];
        sc[0] = e[0]; sc[1] = sc[0] + e[1]; sc[2] = sc[1] + e[2]; sc[3] = sc[2] + e[3];
        float v = sc[3];
#pragma unroll
        for (int d = 1; d < 32; d <<= 1) {
            float t2 = __shfl_up_sync(0xffffffffu, v, d);
            if (lane >= d) v += t2;
        }
        float base = v - sc[3];
        float cj[4];
#pragma unroll
        for (int j = 0; j < 4; j++) cj[j] = base + sc[j];

        float x[4], m[4];
#pragma unroll
        for (int j = 0; j < 4; j++) {
            int idx = idx0 + j;
            x[j] = (idx < UP1) ? (a[j] + lbv[j] - cj[j]) : BIG;
        }
        m[0] = x[0];
        m[1] = lsef(m[0], x[1]);
        m[2] = lsef(m[1], x[2]);
        m[3] = lsef(m[2], x[3]);
        float z = m[3];
#pragma unroll
        for (int d = 1; d < 32; d <<= 1) {
            float t2 = __shfl_up_sync(0xffffffffu, z, d);
            if (lane >= d) z = lsef(z, t2);
        }
        float excl = __shfl_up_sync(0xffffffffu, z, 1);
        if (lane == 0) excl = BIG;
#pragma unroll
        for (int j = 0; j < 4; j++) a[j] = cj[j] + lsef(excl, m[j]);

#pragma unroll
        for (int j = 0; j < 4; j++) { e[j] = en[j]; lbv[j] = lbn[j]; }
    }

    float sel = a[ul & 3];
    float aul = __shfl_sync(0xffffffffu, sel, ul >> 2);
    if (lane == 0)
        g_nll[b] = -(aul + __ldg(&lbB[(size_t)(tl - 1) * UP1 + ul]));
}

__global__ void mean_kernel(float* __restrict__ out)
{
    float s = 0.f;
    for (int b = 0; b < Bq; b++) s += g_nll[b];
    out[0] = s / (float)Bq;
}

// ---------------- launch ----------------
static void launch_lstm16(cudaStream_t st, const float* Whh, const float* xp,
                          float* ho, int T)
{
    cudaLaunchConfig_t cfg = {};
    cfg.gridDim = dim3(16 * Bq, 1, 1);     // 8 clusters of 16 CTAs
    cfg.blockDim = dim3(320, 1, 1);
    cfg.dynamicSmemBytes = 0;
    cfg.stream = st;
    cudaLaunchAttribute attrs[1];
    attrs[0].id = cudaLaunchAttributeClusterDimension;
    attrs[0].val.clusterDim = {16, 1, 1};
    cfg.attrs = attrs;
    cfg.numAttrs = 1;
    cudaLaunchKernelEx(&cfg, lstm16_kernel, Whh, xp, ho, T);
}

extern "C" void kernel_launch(void* const* d_in, const int* in_sizes, int n_in,
                              void* d_out, int out_size)
{
    const float* xs    = (const float*)d_in[0];
    const int*   ys    = (const int*)  d_in[1];
    const int*   xlen  = (const int*)  d_in[2];
    const int*   ylen  = (const int*)  d_in[3];
    const float* eWih0 = (const float*)d_in[4];
    const float* eWhh0 = (const float*)d_in[5];
    const float* ebih0 = (const float*)d_in[6];
    const float* ebhh0 = (const float*)d_in[7];
    const float* eWih1 = (const float*)d_in[8];
    const float* eWhh1 = (const float*)d_in[9];
    const float* ebih1 = (const float*)d_in[10];
    const float* ebhh1 = (const float*)d_in[11];
    const float* eWo   = (const float*)d_in[12];
    const float* ebo   = (const float*)d_in[13];
    /* d_in[14] = embed (one-hot; folded into xpd gather) */
    const float* dWih  = (const float*)d_in[15];
    const float* dWhh  = (const float*)d_in[16];
    const float* dbih  = (const float*)d_in[17];
    const float* dbhh  = (const float*)d_in[18];
    const float* dWo   = (const float*)d_in[19];
    const float* dbo   = (const float*)d_in[20];
    float* out = (float*)d_out;

    float *xp0, *h0, *xp1, *h1, *enc, *xpd, *hd, *dec;
    cudaGetSymbolAddress((void**)&xp0, g_xp0);
    cudaGetSymbolAddress((void**)&h0,  g_h0);
    cudaGetSymbolAddress((void**)&xp1, g_xp1);
    cudaGetSymbolAddress((void**)&h1,  g_h1);
    cudaGetSymbolAddress((void**)&enc, g_enc);
    cudaGetSymbolAddress((void**)&xpd, g_xpd);
    cudaGetSymbolAddress((void**)&hd,  g_hd);
    cudaGetSymbolAddress((void**)&dec, g_dec);

    static cudaStream_t s1 = nullptr;
    static cudaEvent_t Efork, Edec;
    static int inited = 0;
    if (!inited) {
        cudaStreamCreateWithFlags(&s1, cudaStreamNonBlocking);
        cudaEventCreateWithFlags(&Efork, cudaEventDisableTiming);
        cudaEventCreateWithFlags(&Edec, cudaEventDisableTiming);
        cudaFuncSetAttribute(lstm16_kernel,
                             cudaFuncAttributeNonPortableClusterSizeAllowed, 1);
        inited = 1;
    }

    const int MT = Bq * Tq;       // 4000
    const int MU = Bq * UP1;      // 968
    cudaStream_t s0 = 0;

    cudaEventRecord(Efork, s0);
    cudaStreamWaitEvent(s1, Efork, 0);

    // side stream: decoder branch (xpd -> dec LSTM -> dec proj)
    xpd_kernel<<<Bq * UP1, 256, 0, s1>>>(ys, dWih, dbih, dbhh);
    launch_lstm16(s1, dWhh, xpd, hd, DTq);
    gemm_nt<<<dim3(Vq / GBN, (MU + GBM - 1) / GBM), 256, 0, s1>>>(
        hd, dWo, dbo, nullptr, dec, MU, Vq, Hq);
    cudaEventRecord(Edec, s1);

    // main chain: encoder
    gemm_nt<<<dim3(G4 / GBN, (MT + GBM - 1) / GBM), 256, 0, s0>>>(
        xs, eWih0, ebih0, ebhh0, xp0, MT, G4, DIN);
    launch_lstm16(s0, eWhh0, xp0, h0, Tq);
    gemm_nt<<<dim3(G4 / GBN, (MT + GBM - 1) / GBM), 256, 0, s0>>>(
        h0, eWih1, ebih1, ebhh1, xp1, MT, G4, Hq);
    launch_lstm16(s0, eWhh1, xp1, h1, Tq);
    gemm_nt<<<dim3(Vq / GBN, (MT + GBM - 1) / GBM), 256, 0, s0>>>(
        h1, eWo, ebo, nullptr, enc, MT, Vq, Hq);

    // join, then joint/alpha/mean
    cudaStreamWaitEvent(s0, Edec, 0);
    joint_kernel<<<dim3(Tq / 4, Bq), 128, 0, s0>>>(ys);
    alpha_kernel<<<Bq, 32, 0, s0>>>(xlen, ylen);
    mean_kernel<<<1, 1, 0, s0>>>(out);
}